// round 17
// baseline (speedup 1.0000x reference)
#include <cuda_runtime.h>
#include <cstdint>

// ---------------------------------------------------------------------------
// Skeletonize — bit-packed u64, X-contiguous rows, paired-offset fusion.
//   storage: g_img[((b*162 + Y)*162 + X)*3 + w]  (X fastest among columns)
//   Each thinning iteration: 1 endpoint + 4 fused (xo=0 then xo=1) kernels.
//   RNG: JAX threefry_partitionable: counter (0, flat_index), bits = o0 ^ o1
// ---------------------------------------------------------------------------

#define NPAD 162
#define WPR 3
#define HALF 4251528u                   // 162^3
#define ROWU 486                        // 162*3 u64 per (b,Y) line

typedef unsigned long long u64;
typedef unsigned int u32;

__device__ u64 g_img[2*NPAD*ROWU];
__device__ u64 g_end[2*NPAD*ROWU];

__device__ __forceinline__ u32 rotl32(u32 x, int r){ return (x<<r)|(x>>(32-r)); }

// JAX threefry2x32, key (0,42), partitionable combine
__device__ __forceinline__ u32 threefry_xor(u32 x0, u32 x1){
  const u32 ks1 = 42u;
  const u32 ks2 = 0x1BD11BDAu ^ 42u;
  x0 += 0u; x1 += ks1;
#define TF_RND(r) { x0 += x1; x1 = rotl32(x1, (r)); x1 ^= x0; }
  TF_RND(13) TF_RND(15) TF_RND(26) TF_RND(6)
  x0 += ks1; x1 += ks2 + 1u;
  TF_RND(17) TF_RND(29) TF_RND(16) TF_RND(24)
  x0 += ks2; x1 += 2u;
  TF_RND(13) TF_RND(15) TF_RND(26) TF_RND(6)
  x0 += 0u;  x1 += ks1 + 3u;
  TF_RND(17) TF_RND(29) TF_RND(16) TF_RND(24)
  x0 += ks1; x1 += ks2 + 4u;
  TF_RND(13) TF_RND(15) TF_RND(26) TF_RND(6)
  x0 += ks2; x1 += 5u;
#undef TF_RND
  return x0 ^ x1;
}

__device__ __forceinline__ int hard_bit(u32 bits, float img){
  float f = __fadd_rn(__uint_as_float((bits >> 9) | 0x3f800000u), -1.0f);
  float u = __fadd_rn(__fmul_rn(f, 1.0f), 1e-8f);
  u = fmaxf(1e-8f, u);
  float noise = __fadd_rn(logf(u), -log1pf(-u));
  float alpha = __fdiv_rn(__fadd_rn(img, 1e-8f),
                          __fadd_rn(__fadd_rn(1.0f, -img), 1e-8f));
  float zv = __fadd_rn(logf(alpha), __fmul_rn(noise, 0.33f));
  return zv > 0.0f;
}

__global__ void k_binarize(const float* __restrict__ in){
  int gt = blockIdx.x*blockDim.x + threadIdx.x;
  int W = gt >> 5;
  int lane = gt & 31;
  if (W >= NPAD*NPAD*6) return;
  int r0 = W / 6, k = W % 6;
  int X = r0 / NPAD, Y = r0 % NPAD;
  int z = k*32 + lane;
  bool valid = (z < NPAD);
  u32 i = (u32)r0 * (u32)NPAD + (u32)(valid ? z : 0);
  u32 b0bits = threefry_xor(0u, i);
  u32 b1bits = threefry_xor(0u, i + HALF);
  bool interior = valid && X>=1 && X<=160 && Y>=1 && Y<=160 && z>=1 && z<=160;
  float v0 = 0.f, v1 = 0.f;
  if (interior){
    int ui = ((X-1)*160 + (Y-1))*160 + (z-1);
    v0 = in[ui];
    v1 = in[ui + 160*160*160];
  }
  int h0 = hard_bit(b0bits, v0);
  int h1 = hard_bit(b1bits, v1);
  u32 m0 = __ballot_sync(0xFFFFFFFFu, valid && h0);
  u32 m1 = __ballot_sync(0xFFFFFFFFu, valid && h1);
  if (lane == 0){
    u32* p = (u32*)g_img;
    p[((size_t)(          Y)*NPAD + X)*6 + k] = m0;              // batch 0
    p[((size_t)(NPAD    + Y)*NPAD + X)*6 + k] = m1;              // batch 1
  }
}

#define SAT(one, ge, x) { u64 _x=(x); (ge) |= (one) & _x; (one) |= _x; }

__device__ __forceinline__ u64 colw_f(const u64 (*Sl)[ROWU], int j, int Xc, int ww){
  return (Xc>=0 && Xc<NPAD && ww>=0 && ww<WPR) ? Sl[j][Xc*3+ww] : 0ull;
}

__device__ __forceinline__ void load_slab3(u64 (*Sl)[ROWU], int b, int Y){
  #pragma unroll
  for (int j=0;j<3;j++){
    int YY = Y + j - 1;
    Sl[j][threadIdx.x] = (YY>=0 && YY<NPAD)
        ? g_img[((size_t)(b*NPAD + YY))*ROWU + threadIdx.x] : 0ull;
  }
}

// full simple predicate on a 3x3x3 view array
__device__ __forceinline__ u64 simple_mask(const u64 A[3][3][3]){
  u64 one18=0, ge18=0;
  #pragma unroll
  for (int i=0;i<3;i++){
    #pragma unroll
    for (int j=0;j<3;j++){
      #pragma unroll
      for (int k=0;k<3;k++){
        int c = (i==1?0:1)+(j==1?0:1)+(k==1?0:1);
        if (c==1 || c==2) SAT(one18, ge18, A[i][j][k]);
      }
    }
  }
  u64 one26=one18, ge26=ge18;
  #pragma unroll
  for (int i=0;i<3;i+=2){
    #pragma unroll
    for (int j=0;j<3;j+=2){
      #pragma unroll
      for (int k=0;k<3;k+=2) SAT(one26, ge26, A[i][j][k]);
    }
  }
  u64 one6=0, ge6=0;
  SAT(one6, ge6, ~A[0][1][1]); SAT(one6, ge6, ~A[2][1][1]);
  SAT(one6, ge6, ~A[1][0][1]); SAT(one6, ge6, ~A[1][2][1]);
  SAT(one6, ge6, ~A[1][1][0]); SAT(one6, ge6, ~A[1][1][2]);
  u64 anyB = 0;
  #pragma unroll
  for (int i=0;i<3;i+=2){
    #pragma unroll
    for (int j=0;j<3;j+=2){
      #pragma unroll
      for (int k=0;k<3;k+=2){
        u64 others = A[i][1][1] | A[1][j][1] | A[1][1][k]
                   | A[i][j][1] | A[i][1][k] | A[1][j][k];
        anyB |= A[i][j][k] & ~others;
      }
    }
  }
  u64 anyA = 0;
  #pragma unroll
  for (int s2=0;s2<3;s2+=2){
    anyA |= ~A[s2][1][1] & A[s2][0][1] & A[s2][2][1] & A[s2][1][0] & A[s2][1][2];
    anyA |= ~A[1][s2][1] & A[0][s2][1] & A[2][s2][1] & A[1][s2][0] & A[1][s2][2];
    anyA |= ~A[1][1][s2] & A[0][1][s2] & A[2][1][s2] & A[1][0][s2] & A[1][2][s2];
  }
  u64 notB = ~anyB;
  return (one6 & ~ge6)
       | (one26 & ~ge26)
       | (one18 & ~ge18 & notB)
       | (ge6 & ~anyA & notB);
}

// ---- endpoint: block per (b, Y); thread (X, w); all taps via smem slab ----
__global__ void __launch_bounds__(ROWU) k_endpoint(){
  __shared__ u64 Sl[3][ROWU];
  int blk = blockIdx.x;                // 0..323
  int Y = blk % NPAD, b = blk / NPAD;
  load_slab3(Sl, b, Y);
  __syncthreads();
  int X = threadIdx.x / 3, w = threadIdx.x % 3;
  u64 one=0, ge=0;
  #pragma unroll
  for (int i=0;i<3;i++){
    #pragma unroll
    for (int j=0;j<3;j++){
      int Xc = X + i - 1;
      u64 wm = colw_f(Sl, j, Xc, w-1);
      u64 wc = colw_f(Sl, j, Xc, w);
      u64 wp = colw_f(Sl, j, Xc, w+1);
      u64 M = (wc<<1) | (wm>>63);
      u64 P = (wc>>1) | (wp<<63);
      SAT(one, ge, M);
      if (!(i==1 && j==1)) SAT(one, ge, wc);
      SAT(one, ge, P);
    }
  }
  g_end[(size_t)blk*ROWU + threadIdx.x] = ~ge;   // bit=1 <=> endpoint
}

// ---- fused pair (xo=0 then xo=1) at fixed (yo, zo) ----
__global__ void __launch_bounds__(ROWU) k_pair(int yo, int zo){
  __shared__ u64 Sl[3][ROWU];
  __shared__ u64 Snew[81][3];
  int blk = blockIdx.x;                // 0..161
  int Yi = blk % 81, b = blk / 81;
  int Y = yo + 2*Yi;
  load_slab3(Sl, b, Y);
  __syncthreads();
  int X = threadIdx.x / 3, w = threadIdx.x % 3;
  u64 zmask = zo ? 0xAAAAAAAAAAAAAAAAull : 0x5555555555555555ull;
  size_t own = ((size_t)(b*NPAD + Y))*ROWU + threadIdx.x;
  u64 notend = ~g_end[own];

  // ---- phase A: xo = 0 (even X) ----
  if ((X & 1) == 0){
    u64 A[3][3][3];
    #pragma unroll
    for (int i=0;i<3;i++){
      #pragma unroll
      for (int j=0;j<3;j++){
        int Xc = X + i - 1;
        u64 wm = colw_f(Sl, j, Xc, w-1);
        u64 wc = colw_f(Sl, j, Xc, w);
        u64 wp = colw_f(Sl, j, Xc, w+1);
        A[i][j][0] = (wc<<1) | (wm>>63);
        A[i][j][1] = wc;
        A[i][j][2] = (wc>>1) | (wp<<63);
      }
    }
    u64 del = simple_mask(A) & notend & zmask;
    u64 neww = A[1][1][1] & ~del;
    Snew[X>>1][w] = neww;
    if (del) g_img[own] = neww;
  }
  __syncthreads();

  // ---- phase B: xo = 1 (odd X); patch columns X-1, X+1 from Snew ----
  if (X & 1){
    u64 A[3][3][3];
    #pragma unroll
    for (int i=0;i<3;i++){
      #pragma unroll
      for (int j=0;j<3;j++){
        int Xc = X + i - 1;
        u64 wm, wc, wp;
        if (j==1 && i!=1 && Xc < NPAD){       // Xc = X-1 or X+1, even, in range
          wm = (w>0)     ? Snew[Xc>>1][w-1] : 0ull;
          wc =             Snew[Xc>>1][w];
          wp = (w<WPR-1) ? Snew[Xc>>1][w+1] : 0ull;
        } else {
          wm = colw_f(Sl, j, Xc, w-1);
          wc = colw_f(Sl, j, Xc, w);
          wp = colw_f(Sl, j, Xc, w+1);
        }
        A[i][j][0] = (wc<<1) | (wm>>63);
        A[i][j][1] = wc;
        A[i][j][2] = (wc>>1) | (wp<<63);
      }
    }
    u64 del = simple_mask(A) & notend & zmask;
    if (del) g_img[own] = A[1][1][1] & ~del;
  }
}

__global__ void k_unpack(float* __restrict__ out){
  int t = blockIdx.x*blockDim.x + threadIdx.x;
  if (t >= 2*160*160) return;
  int y = t % 160; int q = t / 160;
  int x = q % 160; int b = q / 160;
  size_t base = ((size_t)(b*NPAD + (y+1)))*ROWU + (size_t)(x+1)*3;
  u64 w0 = g_img[base], w1 = g_img[base+1], w2 = g_img[base+2];
  u64 a0 = (w0>>1) | (w1<<63);
  u64 a1 = (w1>>1) | (w2<<63);
  u64 a2 = (w2>>1);
  float4* o4 = (float4*)(out + ((size_t)(b*160 + x)*160 + y)*160);
  #pragma unroll
  for (int k = 0; k < 16; k++){
    unsigned nib = (unsigned)((a0 >> (4*k)) & 15ull);
    o4[k] = make_float4((float)(nib&1), (float)((nib>>1)&1),
                        (float)((nib>>2)&1), (float)((nib>>3)&1));
  }
  #pragma unroll
  for (int k = 0; k < 16; k++){
    unsigned nib = (unsigned)((a1 >> (4*k)) & 15ull);
    o4[16+k] = make_float4((float)(nib&1), (float)((nib>>1)&1),
                           (float)((nib>>2)&1), (float)((nib>>3)&1));
  }
  #pragma unroll
  for (int k = 0; k < 8; k++){
    unsigned nib = (unsigned)((a2 >> (4*k)) & 15ull);
    o4[32+k] = make_float4((float)(nib&1), (float)((nib>>1)&1),
                           (float)((nib>>2)&1), (float)((nib>>3)&1));
  }
}

extern "C" void kernel_launch(void* const* d_in, const int* in_sizes, int n_in,
                              void* d_out, int out_size){
  const float* in = (const float*)d_in[0];
  float* out = (float*)d_out;
  (void)in_sizes; (void)n_in; (void)out_size;

  k_binarize<<<19683, 256>>>(in);

  for (int it = 0; it < 5; ++it){
    k_endpoint<<<2*NPAD, ROWU>>>();
    // offset order: (0,0,0),(1,0,0) | (0,1,0),(1,1,0) | (0,0,1),(1,0,1) | (0,1,1),(1,1,1)
    k_pair<<<2*81, ROWU>>>(0, 0);
    k_pair<<<2*81, ROWU>>>(1, 0);
    k_pair<<<2*81, ROWU>>>(0, 1);
    k_pair<<<2*81, ROWU>>>(1, 1);
  }

  k_unpack<<<(2*160*160 + 255)/256, 256>>>(out);
}